// round 17
// baseline (speedup 1.0000x reference)
#include <cuda_runtime.h>
#include <math.h>

// Problem shape (fixed by setup_inputs)
#define Bb   32
#define Hh   64
#define Ww   48
#define Cc   256
#define Dd   32
#define BG   256            // Bb * groups(8)
#define NPIX (Hh*Ww)        // 3072
#define LN_EPS 1e-3f

__device__ __forceinline__ float wsum(float v){
#pragma unroll
    for (int o = 16; o; o >>= 1) v += __shfl_xor_sync(0xffffffffu, v, o);
    return v;
}
__device__ __forceinline__ float wmax(float v){
#pragma unroll
    for (int o = 16; o; o >>= 1) v = fmaxf(v, __shfl_xor_sync(0xffffffffu, v, o));
    return v;
}

// Dynamic smem layout (floats):
#define F_ROW   0                  // s_row[64][32]
#define F_COLP  2048               // s_colp[4][48][32]; AFTER Phase C reused as s_w2[3072]
#define F_XH    8192               // s_xh[64][32]
#define F_XW    10240              // s_xw[48][32]
#define F_W1    11776              // smW[1024]; AFTER Phase B reused as s_weff[288]
#define F_S9    12800              // smS[288]
#define F_SA    13088              // sA[16][32]
#define F_SB    13600              // sB[16]
#define F_X11   13616              // x11[32]
#define F_C     13648              // s_c[32]  (x21*gamma)
#define F_SC    13680              // s_scal[4] (csum, cb, beff)
#define F_TOTAL 13684              // floats -> 54736 bytes

// ---------------------------------------------------------------------------
// GRAND FUSED kernel: pools, gates, x21/x11 softmaxes, LN stats, w2 field,
// projected conv + gate + output — one block (512 thr, 16 warps) per bg.
// launch_bounds(512,2): 2 blocks/SM -> all 256 blocks in ONE wave.
// ---------------------------------------------------------------------------
__global__ void __launch_bounds__(512, 2)
fused_all(const float* __restrict__ x,
          const float* __restrict__ w1x1,
          const float* __restrict__ b1,
          const float* __restrict__ w3,
          const float* __restrict__ b3,
          const float* __restrict__ gamma,
          const float* __restrict__ beta,
          float* __restrict__ out)
{
    extern __shared__ float sm[];
    float (*s_row)[Dd]       = (float(*)[Dd])(sm + F_ROW);
    float (*s_colp)[Ww][Dd]  = (float(*)[Ww][Dd])(sm + F_COLP);
    float (*s_xh)[Dd]        = (float(*)[Dd])(sm + F_XH);
    float (*s_xw)[Dd]        = (float(*)[Dd])(sm + F_XW);
    float *smW = sm + F_W1;
    float *smS = sm + F_S9;
    float (*sA)[Dd]          = (float(*)[Dd])(sm + F_SA);
    float *sB  = sm + F_SB;
    float *x11 = sm + F_X11;
    float *s_c = sm + F_C;
    float *s_scal = sm + F_SC;
    float *s_w2   = sm + F_COLP;   // overlay (valid after Phase C)
    float *s_weff = sm + F_W1;     // overlay (valid after Phase B)

    int bg = blockIdx.x;
    int b = bg >> 3, gi = bg & 7;
    int tid = threadIdx.x, lane = tid & 31, warp = tid >> 5;   // 16 warps
    int sg = lane >> 3, ch0 = (lane & 7) * 4;
    const float* xg = x + ((size_t)b*Hh)*Ww*Cc + gi*Dd + ch0;  // float4 base
    const float* xb = x + ((size_t)b*Hh)*Ww*Cc + gi*Dd + lane; // scalar base

    // stage conv1x1 weights (sync provided by the staged col-reduce below)
    for (int i = tid; i < Dd*Dd; i += 512) smW[i] = w1x1[i];

    // ---- Phase A: row means + col sums. Superslab structure (low regs). ----
    {
        float4 racc[4];
#pragma unroll
        for (int rr = 0; rr < 4; ++rr) racc[rr] = make_float4(0.f,0.f,0.f,0.f);
        int r0w = warp * 4;
        int slot = warp & 3, grp = warp >> 2;
#pragma unroll
        for (int ss = 0; ss < 3; ++ss) {
            float4 cacc[4];
#pragma unroll
            for (int s = 0; s < 4; ++s) cacc[s] = make_float4(0.f,0.f,0.f,0.f);
#pragma unroll
            for (int rr = 0; rr < 4; ++rr) {
                const float* rp = xg + (size_t)(r0w + rr)*Ww*Cc;
#pragma unroll
                for (int s = 0; s < 4; ++s) {
                    float4 v = *(const float4*)(rp + (size_t)(ss*16 + s*4 + sg)*Cc);
                    cacc[s].x += v.x; cacc[s].y += v.y; cacc[s].z += v.z; cacc[s].w += v.w;
                    racc[rr].x += v.x; racc[rr].y += v.y; racc[rr].z += v.z; racc[rr].w += v.w;
                }
            }
            // staged atomic-free cross-warp accumulation into s_colp[slot]
#pragma unroll
            for (int rd = 0; rd < 4; ++rd) {
                if (grp == rd) {
#pragma unroll
                    for (int s = 0; s < 4; ++s) {
                        float4* dst = (float4*)&s_colp[slot][ss*16 + s*4 + sg][ch0];
                        if (rd == 0) *dst = cacc[s];
                        else {
                            float4 t = *dst;
                            t.x += cacc[s].x; t.y += cacc[s].y;
                            t.z += cacc[s].z; t.w += cacc[s].w;
                            *dst = t;
                        }
                    }
                }
                __syncthreads();
            }
        }
        // row means
#pragma unroll
        for (int rr = 0; rr < 4; ++rr) {
            float4 rv = racc[rr];
#pragma unroll
            for (int o = 8; o <= 16; o <<= 1) {
                rv.x += __shfl_xor_sync(0xffffffffu, rv.x, o);
                rv.y += __shfl_xor_sync(0xffffffffu, rv.y, o);
                rv.z += __shfl_xor_sync(0xffffffffu, rv.z, o);
                rv.w += __shfl_xor_sync(0xffffffffu, rv.w, o);
            }
            if (sg == 0) {
                rv.x *= (1.f/Ww); rv.y *= (1.f/Ww); rv.z *= (1.f/Ww); rv.w *= (1.f/Ww);
                *(float4*)&s_row[r0w + rr][ch0] = rv;
            }
        }
    }
    __syncthreads();

    // ---- Phase B (warps 1..15) / Phase C (warp 0), concurrent ----
    if (warp > 0) {
        float bias = b1[lane];
        for (int p = warp - 1; p < Hh + Ww; p += 15) {
            float v;
            if (p < Hh) v = s_row[p][lane];
            else {
                int w = p - Hh;
                v = (s_colp[0][w][lane] + s_colp[1][w][lane]
                   + s_colp[2][w][lane] + s_colp[3][w][lane]) * (1.0f/Hh);
            }
            float acc = bias;
#pragma unroll
            for (int i = 0; i < Dd; ++i) {
                float vi = __shfl_sync(0xffffffffu, v, i);
                acc += vi * smW[i*Dd + lane];
            }
            float s = __fdividef(1.f, 1.f + __expf(-acc));
            if (p < Hh) s_xh[p][lane] = s;
            else        s_xw[p-Hh][lane] = s;
        }
    } else {
        int i = lane;
        float T = 0.f;
#pragma unroll 8
        for (int h = 0; h < Hh; ++h) T += s_row[h][i];
        T *= (float)Ww;
        float R0 = s_row[0     ][i] * (float)Ww;
        float RL = s_row[Hh - 1][i] * (float)Ww;
        float C0 = s_colp[0][0][i] + s_colp[1][0][i] + s_colp[2][0][i] + s_colp[3][0][i];
        float CL = s_colp[0][Ww-1][i] + s_colp[1][Ww-1][i] + s_colp[2][Ww-1][i] + s_colp[3][Ww-1][i];
        float ctl = xb[0];
        float ctr = xb[(size_t)(Ww-1)*Cc];
        float cbl = xb[((size_t)(Hh-1)*Ww)*Cc];
        float cbr = xb[((size_t)(Hh-1)*Ww + (Ww-1))*Cc];
#pragma unroll
        for (int dy = -1; dy <= 1; ++dy) {
#pragma unroll
            for (int dx = -1; dx <= 1; ++dx) {
                float eR = (dy == -1) ? RL : (dy == 1) ? R0 : 0.f;
                float eC = (dx == -1) ? CL : (dx == 1) ? C0 : 0.f;
                float corner = 0.f;
                if (dy == -1 && dx == -1) corner = cbr;
                if (dy == -1 && dx ==  1) corner = cbl;
                if (dy ==  1 && dx == -1) corner = ctr;
                if (dy ==  1 && dx ==  1) corner = ctl;
                smS[((dy+1)*3 + (dx+1))*Dd + i] = T - eR - eC + corner;
            }
        }
        __syncwarp();
        int e = lane;
        float acc = 0.f;
        for (int k = 0; k < 9; ++k) {
#pragma unroll
            for (int ii = 0; ii < Dd; ++ii)
                acc += w3[(k*Dd + ii)*Dd + e] * smS[k*Dd + ii];
        }
        float m2 = acc * (1.f/NPIX) + b3[e];
        float mx = wmax(m2);
        float pz = expf(m2 - mx);
        float ps = wsum(pz);
        float x21 = pz/ps;
        float cv = x21 * gamma[e];
        s_c[e] = cv;
        float cs  = wsum(cv);
        float cbv = wsum(x21 * beta[e]);
        if (e == 0) { s_scal[0] = cs; s_scal[1] = cbv; }
    }
    __syncthreads();
    // s_colp is dead from here on: its space becomes s_w2

    // ---- Phase D: LN-stat sweep + w2 field, SOFTWARE-PIPELINED loads,
    //      incremental (h,w) indexing (no divides). ----
    {
        float4 cvq = *(const float4*)&s_c[ch0];
        float csum = s_scal[0], cb = s_scal[1];
        float4 accA = make_float4(0.f,0.f,0.f,0.f);
        float accB = 0.f;
        const float4 z = make_float4(0.f,0.f,0.f,0.f);

        int h = warp * 4, w = sg;               // p = h*Ww + w; w steps by 4
        const float* xp = xg + (size_t)(warp*192 + sg)*Cc;
        float4 gx = *(const float4*)xp;
        float4 xh = *(const float4*)&s_xh[h][ch0];
        float4 xw = *(const float4*)&s_xw[w][ch0];

        for (int j = 0; j < 48; ++j) {
            // 1) prefetch pixel j+1 (consumed next iteration)
            int w_n = w + 4, h_n = h;
            if (w_n >= Ww) { w_n -= Ww; h_n += 1; }
            float4 gx_n = z, xh_n = z, xw_n = z;
            if (j < 47) {
                xp += 4*Cc;
                gx_n = *(const float4*)xp;
                xh_n = *(const float4*)&s_xh[h_n][ch0];
                xw_n = *(const float4*)&s_xw[w_n][ch0];
            }

            // 2) compute pixel j (loaded LAST iteration)
            float4 y;
            y.x = gx.x*xh.x*xw.x; y.y = gx.y*xh.y*xw.y;
            y.z = gx.z*xh.z*xw.z; y.w = gx.w*xh.w*xw.w;
            float a  = (y.x + y.y) + (y.z + y.w);
            float bq = (y.x*y.x + y.y*y.y) + (y.z*y.z + y.w*y.w);
            float cy = (cvq.x*y.x + cvq.y*y.y) + (cvq.z*y.z + cvq.w*y.w);
#pragma unroll
            for (int o = 4; o; o >>= 1) {
                a  += __shfl_xor_sync(0xffffffffu, a,  o);
                bq += __shfl_xor_sync(0xffffffffu, bq, o);
                cy += __shfl_xor_sync(0xffffffffu, cy, o);
            }
            float mu = a * (1.f/Dd);
            float var = bq * (1.f/Dd) - mu*mu;
            float rs = rsqrtf(var + LN_EPS);
            accA.x += rs*y.x; accA.y += rs*y.y; accA.z += rs*y.z; accA.w += rs*y.w;
            accB += rs*mu;
            float w2v = rs * (cy - mu*csum) + cb;
            if ((lane & 7) == 0) s_w2[h*Ww + w] = w2v;

            // 3) rotate
            h = h_n; w = w_n;
            gx = gx_n; xh = xh_n; xw = xw_n;
        }
#pragma unroll
        for (int o = 8; o <= 16; o <<= 1) {
            accA.x += __shfl_xor_sync(0xffffffffu, accA.x, o);
            accA.y += __shfl_xor_sync(0xffffffffu, accA.y, o);
            accA.z += __shfl_xor_sync(0xffffffffu, accA.z, o);
            accA.w += __shfl_xor_sync(0xffffffffu, accA.w, o);
        }
        if (sg == 0) *(float4*)&sA[warp][ch0] = accA;
        float bt = wsum(accB) * 0.125f;   // each pixel counted by 8 lanes
        if (lane == 0) sB[warp] = bt;
    }
    __syncthreads();

    // ---- Phase E: x11 softmax + beff (warp 0), then weff into smem ----
    if (warp == 0) {
        int e = lane;
        float A = 0.f, Bs = 0.f;
#pragma unroll
        for (int k = 0; k < 16; ++k) { A += sA[k][e]; Bs += sB[k]; }
        float v = gamma[e] * (A - Bs) * (1.f/NPIX) + beta[e];
        float mx = wmax(v);
        float p = expf(v - mx);
        float ps = wsum(p);
        float xv = p/ps;
        x11[e] = xv;
        float be = wsum(xv * b3[e]);
        if (e == 0) s_scal[2] = be;
    }
    __syncthreads();
    if (tid < 288) {
        const float4* wrow = (const float4*)(w3 + (size_t)tid*Dd);
        float acc = 0.f;
#pragma unroll
        for (int e4 = 0; e4 < 8; ++e4) {
            float4 wv = __ldg(&wrow[e4]);
            acc += wv.x*x11[e4*4+0] + wv.y*x11[e4*4+1]
                 + wv.z*x11[e4*4+2] + wv.w*x11[e4*4+3];
        }
        s_weff[tid] = acc;   // overlays smW (dead after Phase B)
    }
    __syncthreads();

    // ---- Phase F: DOUBLE-BUFFERED conv march along w + gate + output.
    // 2 rows/warp x 16 lanes x float2 channels; taps in 18 registers.
    // Loads for column W+1 issue before row-dots consume column W. ----
    {
        int cl = lane & 15, rr = lane >> 4;     // channel group / row-in-pair
        int ch = cl * 2;
        float2 wk2[9];
#pragma unroll
        for (int k = 0; k < 9; ++k)
            wk2[k] = *(const float2*)&s_weff[k*Dd + ch];
        float beff = s_scal[2];
        const int CS = Cc/2;                    // column stride (float2)
        const int RS = Ww*Cc/2;                 // row stride (float2)

#pragma unroll
        for (int m = 0; m < 2; ++m) {
            int r = m*32 + warp*2 + rr;         // 0..63
            const float2* rq = (const float2*)(x + ((size_t)b*Hh + r)*Ww*Cc + gi*Dd + ch);
            float2* oq = (float2*)(out + ((size_t)b*Hh + r)*Ww*Cc + gi*Dd + ch);
            const float* w2row = s_w2 + r*Ww;
            bool up = (r > 0), dn = (r < Hh-1);

            const float2 z2 = make_float2(0.f,0.f);
            float2 a0 = z2, a1 = z2, pend = z2, g1 = z2, g2 = z2;
            // preload column 0
            float2 c0 = rq[0];
            float2 cm = up ? rq[-RS] : z2;
            float2 cp = dn ? rq[ RS] : z2;
            rq += CS;

            for (int W = 0; W < 50; ++W) {
                // 1) prefetch taps for column W+1 (consumed next iteration)
                float2 n0 = z2, nm = z2, np = z2;
                if (W + 1 < Ww) {
                    n0 = rq[0];
                    if (up) nm = rq[-RS];
                    if (dn) np = rq[ RS];
                }
                rq += CS;

                // 2) emission for output column W-2 (uses only prior-step state;
                //    w2 read directly from smem, hidden under the shfl ladder)
                if (W >= 2) {
                    float w2v = w2row[W-2];
                    float conv = pend.x + pend.y;
                    conv += __shfl_xor_sync(0xffffffffu, conv, 8);
                    conv += __shfl_xor_sync(0xffffffffu, conv, 4);
                    conv += __shfl_xor_sync(0xffffffffu, conv, 2);
                    conv += __shfl_xor_sync(0xffffffffu, conv, 1);
                    float gate = __fdividef(1.f, 1.f + __expf(-(conv + beff + w2v)));
                    float2 o2;
                    o2.x = g2.x*gate; o2.y = g2.y*gate;
                    __stcs(oq, o2);
                    oq += CS;
                }

                // 3) column-dots for column W (loaded LAST iteration)
                float2 rA, rB, rC;
                rA.x = wk2[2].x*cm.x + wk2[5].x*c0.x + wk2[8].x*cp.x;
                rA.y = wk2[2].y*cm.y + wk2[5].y*c0.y + wk2[8].y*cp.y;
                rB.x = wk2[1].x*cm.x + wk2[4].x*c0.x + wk2[7].x*cp.x;
                rB.y = wk2[1].y*cm.y + wk2[4].y*c0.y + wk2[7].y*cp.y;
                rC.x = wk2[0].x*cm.x + wk2[3].x*c0.x + wk2[6].x*cp.x;
                rC.y = wk2[0].y*cm.y + wk2[3].y*c0.y + wk2[6].y*cp.y;

                // 4) rotate pipeline state
                pend.x = a0.x + rA.x; pend.y = a0.y + rA.y;
                a0.x = a1.x + rB.x; a0.y = a1.y + rB.y;
                a1 = rC;
                g2 = g1; g1 = c0;
                cm = nm; c0 = n0; cp = np;
            }
        }
    }
}

// ---------------------------------------------------------------------------
extern "C" void kernel_launch(void* const* d_in, const int* in_sizes, int n_in,
                              void* d_out, int out_size)
{
    const float* x   = (const float*)d_in[0];
    const float* w1  = (const float*)d_in[1];
    const float* b1  = (const float*)d_in[2];
    const float* w3  = (const float*)d_in[3];
    const float* b3  = (const float*)d_in[4];
    const float* gm  = (const float*)d_in[5];
    const float* bt  = (const float*)d_in[6];
    float* out = (float*)d_out;

    static int configured = 0;
    if (!configured) {
        cudaFuncSetAttribute(fused_all, cudaFuncAttributeMaxDynamicSharedMemorySize,
                             F_TOTAL * 4);
        configured = 1;
    }

    fused_all<<<BG, 512, F_TOTAL*4>>>(x, w1, b1, w3, b3, gm, bt, out);
}